// round 1
// baseline (speedup 1.0000x reference)
#include <cuda_runtime.h>
#include <math.h>

// Problem constants
#define BATCH 4
#define TSEQ  4096
#define DMODEL 1024
#define HDIM  64
#define NROWS (BATCH*TSEQ)        // 16384
#define TQ 16                     // q rows per CTA (score / av kernels)
#define KC 128                    // k chunk

// Scratch (device globals — no allocations allowed)
__device__ float g_q[NROWS*HDIM];
__device__ float g_k[NROWS*HDIM];
__device__ float g_v[NROWS*HDIM];
__device__ float g_rowsum[NROWS];
__device__ float g_ent;

__global__ void zero_kernel() { g_ent = 0.0f; }

// ---------------------------------------------------------------------------
// K1: QKV projection.  out[r][h] = sum_c x[r][c] * W[h][c]
// grid (NROWS/64, 3), 256 threads. CTA tile 64 rows x 64 cols, micro 4x4.
// ---------------------------------------------------------------------------
__global__ __launch_bounds__(256) void proj_kernel(
    const float* __restrict__ x,
    const float* __restrict__ Wq,
    const float* __restrict__ Wk,
    const float* __restrict__ Wv)
{
    __shared__ float sX[32*68];   // [c][r] transposed, stride 68
    __shared__ float sW[32*68];   // [c][h] transposed

    const float* W   = (blockIdx.y == 0) ? Wq : ((blockIdx.y == 1) ? Wk : Wv);
    float*       out = (blockIdx.y == 0) ? g_q : ((blockIdx.y == 1) ? g_k : g_v);

    const int row0 = blockIdx.x * 64;
    const int tid  = threadIdx.x;
    const int cg   = tid & 15;    // col group (4 cols)
    const int rg   = tid >> 4;    // row group (4 rows)

    float acc[4][4];
    #pragma unroll
    for (int i = 0; i < 4; i++)
        #pragma unroll
        for (int j = 0; j < 4; j++) acc[i][j] = 0.0f;

    for (int c0 = 0; c0 < DMODEL; c0 += 32) {
        __syncthreads();
        #pragma unroll
        for (int i = 0; i < 8; i++) {       // X tile 64x32 -> sX[c][r]
            int e = tid + i*256;
            int r = e >> 5, c = e & 31;
            sX[c*68 + r] = x[(size_t)(row0 + r)*DMODEL + c0 + c];
        }
        #pragma unroll
        for (int i = 0; i < 8; i++) {       // W tile 64x32 -> sW[c][h]
            int e = tid + i*256;
            int h = e >> 5, c = e & 31;
            sW[c*68 + h] = W[(size_t)h*DMODEL + c0 + c];
        }
        __syncthreads();
        #pragma unroll
        for (int cc = 0; cc < 32; cc++) {
            float4 a = *(const float4*)&sX[cc*68 + 4*rg];
            float4 b = *(const float4*)&sW[cc*68 + 4*cg];
            float av[4] = {a.x, a.y, a.z, a.w};
            float bv[4] = {b.x, b.y, b.z, b.w};
            #pragma unroll
            for (int i = 0; i < 4; i++)
                #pragma unroll
                for (int j = 0; j < 4; j++) acc[i][j] += av[i] * bv[j];
        }
    }

    #pragma unroll
    for (int i = 0; i < 4; i++) {
        float4 v = make_float4(acc[i][0], acc[i][1], acc[i][2], acc[i][3]);
        *(float4*)&out[(size_t)(row0 + 4*rg + i)*HDIM + 4*cg] = v;
    }
}

// ---------------------------------------------------------------------------
// K2: scores.  E[b][q][k] = exp( (q . k) / 8 ), unnormalized, + row sums.
// grid (TSEQ/TQ, BATCH), 256 threads. Each CTA owns TQ full rows of K-range.
// micro: 4q x 2k per thread.
// ---------------------------------------------------------------------------
__global__ __launch_bounds__(256) void score_kernel(float* __restrict__ attn)
{
    __shared__ float sQ[64*20];    // [h][q], stride 20
    __shared__ float sK[64*132];   // [h][k], stride 132
    __shared__ float wred[8][4];

    const int b   = blockIdx.y;
    const int q0  = blockIdx.x * TQ;
    const int tid = threadIdx.x;
    const int kg  = tid & 63;      // 2 k each -> 128
    const int qg  = tid >> 6;      // 4 q each -> 16

    const float* Qp = g_q + ((size_t)b*TSEQ + q0)*HDIM;
    #pragma unroll
    for (int i = 0; i < 4; i++) {           // Q tile 16x64 -> sQ[h][q]
        int e = tid + i*256;
        int q = e >> 6, h = e & 63;
        sQ[h*20 + q] = Qp[(size_t)q*HDIM + h];
    }

    float rsum[4] = {0.f, 0.f, 0.f, 0.f};
    float* arow = attn + ((size_t)b*TSEQ + q0)*TSEQ;

    for (int k0 = 0; k0 < TSEQ; k0 += KC) {
        __syncthreads();
        const float* Kp = g_k + ((size_t)b*TSEQ + k0)*HDIM;
        #pragma unroll
        for (int i = 0; i < 32; i++) {      // K tile 128x64 -> sK[h][k]
            int e = tid + i*256;
            int kk = e >> 6, h = e & 63;
            sK[h*132 + kk] = Kp[(size_t)kk*HDIM + h];
        }
        __syncthreads();

        float s[4][2];
        #pragma unroll
        for (int i = 0; i < 4; i++) { s[i][0] = 0.f; s[i][1] = 0.f; }

        #pragma unroll
        for (int cc = 0; cc < 64; cc++) {
            float4 a  = *(const float4*)&sQ[cc*20 + 4*qg];
            float2 bb = *(const float2*)&sK[cc*132 + 2*kg];
            float av[4] = {a.x, a.y, a.z, a.w};
            #pragma unroll
            for (int i = 0; i < 4; i++) {
                s[i][0] += av[i] * bb.x;
                s[i][1] += av[i] * bb.y;
            }
        }
        #pragma unroll
        for (int i = 0; i < 4; i++) {
            float e0 = __expf(s[i][0] * 0.125f);
            float e1 = __expf(s[i][1] * 0.125f);
            rsum[i] += e0 + e1;
            *(float2*)&arow[(size_t)(4*qg + i)*TSEQ + k0 + 2*kg] = make_float2(e0, e1);
        }
    }

    // reduce rsum across the 64 threads (2 warps) sharing each qg
    #pragma unroll
    for (int i = 0; i < 4; i++)
        #pragma unroll
        for (int off = 16; off > 0; off >>= 1)
            rsum[i] += __shfl_xor_sync(0xffffffffu, rsum[i], off);
    const int w = tid >> 5, lane = tid & 31;
    if (lane == 0) {
        #pragma unroll
        for (int i = 0; i < 4; i++) wred[w][i] = rsum[i];
    }
    __syncthreads();
    if (tid < 16) {
        int qg2 = tid >> 2, i = tid & 3;
        float tot = wred[2*qg2][i] + wred[2*qg2 + 1][i];
        g_rowsum[(size_t)b*TSEQ + q0 + 4*qg2 + i] = tot;
    }
}

// ---------------------------------------------------------------------------
// K3: normalize attn in place, entropy partials, out = P @ V.
// grid (TSEQ/TQ, BATCH), 256 threads. 4 k-split groups of 64 threads; each
// group: out micro 4q x 4h; cross-group reduction at end via smem reuse.
// ---------------------------------------------------------------------------
__global__ __launch_bounds__(256) void av_kernel(float* __restrict__ attn,
                                                 float* __restrict__ out)
{
    __shared__ float sV[KC*68];    // [k][h], stride 68  (reused as redbuf)
    __shared__ float sP[KC*20];    // [k][q], stride 20
    __shared__ float sInv[TQ];
    __shared__ float ered[8];

    const int b   = blockIdx.y;
    const int q0  = blockIdx.x * TQ;
    const int tid = threadIdx.x;

    if (tid < TQ) sInv[tid] = 1.0f / g_rowsum[(size_t)b*TSEQ + q0 + tid];
    __syncthreads();

    // E-phase mapping
    const int kg4  = tid & 31;     // float4 column group
    const int qrow = tid >> 5;     // rows qrow and qrow+8
    const float inv0 = sInv[qrow];
    const float inv1 = sInv[qrow + 8];
    // AV-phase mapping
    const int g  = tid >> 6;       // k-split group 0..3
    const int u  = tid & 63;
    const int hg = u & 15;         // 4 h cols
    const int qg = u >> 4;         // 4 q rows

    float acc[4][4];
    #pragma unroll
    for (int i = 0; i < 4; i++)
        #pragma unroll
        for (int j = 0; j < 4; j++) acc[i][j] = 0.0f;
    float eacc = 0.0f;

    float* arow = attn + ((size_t)b*TSEQ + q0)*TSEQ;

    for (int k0 = 0; k0 < TSEQ; k0 += KC) {
        __syncthreads();
        const float* Vp = g_v + ((size_t)b*TSEQ + k0)*HDIM;
        #pragma unroll
        for (int i = 0; i < 32; i++) {          // V tile 128x64
            int e = tid + i*256;
            int kk = e >> 6, h = e & 63;
            sV[kk*68 + h] = Vp[(size_t)kk*HDIM + h];
        }
        #pragma unroll
        for (int m = 0; m < 2; m++) {           // E tile: normalize + entropy
            int q = qrow + m*8;
            float inv = m ? inv1 : inv0;
            float* ep = &arow[(size_t)q*TSEQ + k0 + 4*kg4];
            float4 e4 = *(const float4*)ep;
            float p0 = e4.x*inv, p1 = e4.y*inv, p2 = e4.z*inv, p3 = e4.w*inv;
            eacc += p0*__logf(p0 + 1e-8f) + p1*__logf(p1 + 1e-8f)
                  + p2*__logf(p2 + 1e-8f) + p3*__logf(p3 + 1e-8f);
            *(float4*)ep = make_float4(p0, p1, p2, p3);
            int kk = 4*kg4;
            sP[(kk+0)*20 + q] = p0;
            sP[(kk+1)*20 + q] = p1;
            sP[(kk+2)*20 + q] = p2;
            sP[(kk+3)*20 + q] = p3;
        }
        __syncthreads();
        const int kbase = g*32;
        #pragma unroll
        for (int t = 0; t < 32; t++) {
            int kk = kbase + t;
            float4 p = *(const float4*)&sP[kk*20 + 4*qg];
            float4 v = *(const float4*)&sV[kk*68 + 4*hg];
            float pv[4] = {p.x, p.y, p.z, p.w};
            float vv[4] = {v.x, v.y, v.z, v.w};
            #pragma unroll
            for (int i = 0; i < 4; i++)
                #pragma unroll
                for (int j = 0; j < 4; j++) acc[i][j] += pv[i] * vv[j];
        }
    }

    // cross-group reduction of out accumulators (reuse sV as scratch)
    __syncthreads();
    float* red = sV;               // needs 4*1024 floats = 16KB <= sV size
    #pragma unroll
    for (int i = 0; i < 4; i++)
        #pragma unroll
        for (int j = 0; j < 4; j++)
            red[g*1024 + (4*qg + i)*64 + 4*hg + j] = acc[i][j];
    __syncthreads();
    #pragma unroll
    for (int m = 0; m < 4; m++) {
        int e = tid + m*256;
        float v = red[e] + red[1024 + e] + red[2048 + e] + red[3072 + e];
        out[((size_t)b*TSEQ + q0 + (e >> 6))*HDIM + (e & 63)] = v;
    }

    // entropy reduction -> one atomicAdd per CTA
    #pragma unroll
    for (int off = 16; off > 0; off >>= 1)
        eacc += __shfl_xor_sync(0xffffffffu, eacc, off);
    if ((tid & 31) == 0) ered[tid >> 5] = eacc;
    __syncthreads();
    if (tid == 0) {
        float t = 0.f;
        #pragma unroll
        for (int w = 0; w < 8; w++) t += ered[w];
        atomicAdd(&g_ent, t);
    }
}

// ---------------------------------------------------------------------------
// K4: finalize energy EMA
// ---------------------------------------------------------------------------
__global__ void fin_kernel(const float* __restrict__ energy, float* __restrict__ eout)
{
    float ent_mean = -g_ent / (float)NROWS;
    *eout = 0.9f * energy[0] + 0.1f * ent_mean;
}

// ---------------------------------------------------------------------------
extern "C" void kernel_launch(void* const* d_in, const int* in_sizes, int n_in,
                              void* d_out, int out_size)
{
    const float* x      = (const float*)d_in[0];
    const float* Wq     = (const float*)d_in[1];
    const float* Wk     = (const float*)d_in[2];
    const float* Wv     = (const float*)d_in[3];
    const float* energy = (const float*)d_in[4];

    float* out  = (float*)d_out;                               // [B,T,H]
    float* attn = out + (size_t)BATCH*TSEQ*HDIM;               // [B,T,T]
    float* eout = attn + (size_t)BATCH*TSEQ*TSEQ;              // scalar

    zero_kernel<<<1, 1>>>();
    proj_kernel<<<dim3(NROWS/64, 3), 256>>>(x, Wq, Wk, Wv);
    score_kernel<<<dim3(TSEQ/TQ, BATCH), 256>>>(attn);
    av_kernel<<<dim3(TSEQ/TQ, BATCH), 256>>>(attn, out);
    fin_kernel<<<1, 1>>>(energy, eout);
}

// round 2
// speedup vs baseline: 1.0018x; 1.0018x over previous
#include <cuda_runtime.h>
#include <math.h>

// Problem constants
#define BATCH 4
#define TSEQ  4096
#define DMODEL 1024
#define HDIM  64
#define NROWS (BATCH*TSEQ)        // 16384
#define TQ 16                     // q rows per CTA (score / av kernels)
#define KC 128                    // k chunk

// Scratch (device globals — no allocations allowed)
__device__ float g_q[NROWS*HDIM];
__device__ float g_k[NROWS*HDIM];
__device__ float g_v[NROWS*HDIM];
__device__ float g_rowsum[NROWS];
__device__ float g_ent;

__global__ void zero_kernel() { g_ent = 0.0f; }

// ---------------------------------------------------------------------------
// K1: QKV projection.  out[r][h] = sum_c x[r][c] * W[h][c]
// grid (NROWS/64, 3), 256 threads. CTA tile 64 rows x 64 cols, micro 4x4.
// ---------------------------------------------------------------------------
__global__ __launch_bounds__(256) void proj_kernel(
    const float* __restrict__ x,
    const float* __restrict__ Wq,
    const float* __restrict__ Wk,
    const float* __restrict__ Wv)
{
    __shared__ float sX[32*68];   // [c][r] transposed, stride 68
    __shared__ float sW[32*68];   // [c][h] transposed

    const float* W   = (blockIdx.y == 0) ? Wq : ((blockIdx.y == 1) ? Wk : Wv);
    float*       out = (blockIdx.y == 0) ? g_q : ((blockIdx.y == 1) ? g_k : g_v);

    const int row0 = blockIdx.x * 64;
    const int tid  = threadIdx.x;
    const int cg   = tid & 15;    // col group (4 cols)
    const int rg   = tid >> 4;    // row group (4 rows)

    float acc[4][4];
    #pragma unroll
    for (int i = 0; i < 4; i++)
        #pragma unroll
        for (int j = 0; j < 4; j++) acc[i][j] = 0.0f;

    for (int c0 = 0; c0 < DMODEL; c0 += 32) {
        __syncthreads();
        #pragma unroll
        for (int i = 0; i < 8; i++) {       // X tile 64x32 -> sX[c][r]
            int e = tid + i*256;
            int r = e >> 5, c = e & 31;
            sX[c*68 + r] = x[(size_t)(row0 + r)*DMODEL + c0 + c];
        }
        #pragma unroll
        for (int i = 0; i < 8; i++) {       // W tile 64x32 -> sW[c][h]
            int e = tid + i*256;
            int h = e >> 5, c = e & 31;
            sW[c*68 + h] = W[(size_t)h*DMODEL + c0 + c];
        }
        __syncthreads();
        #pragma unroll
        for (int cc = 0; cc < 32; cc++) {
            float4 a = *(const float4*)&sX[cc*68 + 4*rg];
            float4 b = *(const float4*)&sW[cc*68 + 4*cg];
            float av[4] = {a.x, a.y, a.z, a.w};
            float bv[4] = {b.x, b.y, b.z, b.w};
            #pragma unroll
            for (int i = 0; i < 4; i++)
                #pragma unroll
                for (int j = 0; j < 4; j++) acc[i][j] += av[i] * bv[j];
        }
    }

    #pragma unroll
    for (int i = 0; i < 4; i++) {
        float4 v = make_float4(acc[i][0], acc[i][1], acc[i][2], acc[i][3]);
        *(float4*)&out[(size_t)(row0 + 4*rg + i)*HDIM + 4*cg] = v;
    }
}

// ---------------------------------------------------------------------------
// K2: scores.  E[b][q][k] = exp( (q . k) / 8 ), unnormalized, + row sums.
// grid (TSEQ/TQ, BATCH), 256 threads. Each CTA owns TQ full rows of K-range.
// micro: 4q x 2k per thread.
// ---------------------------------------------------------------------------
__global__ __launch_bounds__(256) void score_kernel(float* __restrict__ attn)
{
    __shared__ float sQ[64*20];    // [h][q], stride 20
    __shared__ float sK[64*132];   // [h][k], stride 132
    __shared__ float wred[8][4];

    const int b   = blockIdx.y;
    const int q0  = blockIdx.x * TQ;
    const int tid = threadIdx.x;
    const int kg  = tid & 63;      // 2 k each -> 128
    const int qg  = tid >> 6;      // 4 q each -> 16

    const float* Qp = g_q + ((size_t)b*TSEQ + q0)*HDIM;
    #pragma unroll
    for (int i = 0; i < 4; i++) {           // Q tile 16x64 -> sQ[h][q]
        int e = tid + i*256;
        int q = e >> 6, h = e & 63;
        sQ[h*20 + q] = Qp[(size_t)q*HDIM + h];
    }

    float rsum[4] = {0.f, 0.f, 0.f, 0.f};
    float* arow = attn + ((size_t)b*TSEQ + q0)*TSEQ;

    for (int k0 = 0; k0 < TSEQ; k0 += KC) {
        __syncthreads();
        const float* Kp = g_k + ((size_t)b*TSEQ + k0)*HDIM;
        #pragma unroll
        for (int i = 0; i < 32; i++) {      // K tile 128x64 -> sK[h][k]
            int e = tid + i*256;
            int kk = e >> 6, h = e & 63;
            sK[h*132 + kk] = Kp[(size_t)kk*HDIM + h];
        }
        __syncthreads();

        float s[4][2];
        #pragma unroll
        for (int i = 0; i < 4; i++) { s[i][0] = 0.f; s[i][1] = 0.f; }

        #pragma unroll
        for (int cc = 0; cc < 64; cc++) {
            float4 a  = *(const float4*)&sQ[cc*20 + 4*qg];
            float2 bb = *(const float2*)&sK[cc*132 + 2*kg];
            float av[4] = {a.x, a.y, a.z, a.w};
            #pragma unroll
            for (int i = 0; i < 4; i++) {
                s[i][0] += av[i] * bb.x;
                s[i][1] += av[i] * bb.y;
            }
        }
        #pragma unroll
        for (int i = 0; i < 4; i++) {
            float e0 = __expf(s[i][0] * 0.125f);
            float e1 = __expf(s[i][1] * 0.125f);
            rsum[i] += e0 + e1;
            *(float2*)&arow[(size_t)(4*qg + i)*TSEQ + k0 + 2*kg] = make_float2(e0, e1);
        }
    }

    // reduce rsum across the 64 threads (2 warps) sharing each qg
    #pragma unroll
    for (int i = 0; i < 4; i++)
        #pragma unroll
        for (int off = 16; off > 0; off >>= 1)
            rsum[i] += __shfl_xor_sync(0xffffffffu, rsum[i], off);
    const int w = tid >> 5, lane = tid & 31;
    if (lane == 0) {
        #pragma unroll
        for (int i = 0; i < 4; i++) wred[w][i] = rsum[i];
    }
    __syncthreads();
    if (tid < 16) {
        int qg2 = tid >> 2, i = tid & 3;
        float tot = wred[2*qg2][i] + wred[2*qg2 + 1][i];
        g_rowsum[(size_t)b*TSEQ + q0 + 4*qg2 + i] = tot;
    }
}

// ---------------------------------------------------------------------------
// K3: normalize attn in place, entropy partials, out = P @ V.
// grid (TSEQ/TQ, BATCH), 256 threads. 4 k-split groups of 64 threads; each
// group: out micro 4q x 4h; cross-group reduction at end via smem reuse.
// ---------------------------------------------------------------------------
__global__ __launch_bounds__(256) void av_kernel(float* __restrict__ attn,
                                                 float* __restrict__ out)
{
    __shared__ float sV[KC*68];    // [k][h], stride 68  (reused as redbuf)
    __shared__ float sP[KC*20];    // [k][q], stride 20
    __shared__ float sInv[TQ];
    __shared__ float ered[8];

    const int b   = blockIdx.y;
    const int q0  = blockIdx.x * TQ;
    const int tid = threadIdx.x;

    if (tid < TQ) sInv[tid] = 1.0f / g_rowsum[(size_t)b*TSEQ + q0 + tid];
    __syncthreads();

    // E-phase mapping
    const int kg4  = tid & 31;     // float4 column group
    const int qrow = tid >> 5;     // rows qrow and qrow+8
    const float inv0 = sInv[qrow];
    const float inv1 = sInv[qrow + 8];
    // AV-phase mapping
    const int g  = tid >> 6;       // k-split group 0..3
    const int u  = tid & 63;
    const int hg = u & 15;         // 4 h cols
    const int qg = u >> 4;         // 4 q rows

    float acc[4][4];
    #pragma unroll
    for (int i = 0; i < 4; i++)
        #pragma unroll
        for (int j = 0; j < 4; j++) acc[i][j] = 0.0f;
    float eacc = 0.0f;

    float* arow = attn + ((size_t)b*TSEQ + q0)*TSEQ;

    for (int k0 = 0; k0 < TSEQ; k0 += KC) {
        __syncthreads();
        const float* Vp = g_v + ((size_t)b*TSEQ + k0)*HDIM;
        #pragma unroll
        for (int i = 0; i < 32; i++) {          // V tile 128x64
            int e = tid + i*256;
            int kk = e >> 6, h = e & 63;
            sV[kk*68 + h] = Vp[(size_t)kk*HDIM + h];
        }
        #pragma unroll
        for (int m = 0; m < 2; m++) {           // E tile: normalize + entropy
            int q = qrow + m*8;
            float inv = m ? inv1 : inv0;
            float* ep = &arow[(size_t)q*TSEQ + k0 + 4*kg4];
            float4 e4 = *(const float4*)ep;
            float p0 = e4.x*inv, p1 = e4.y*inv, p2 = e4.z*inv, p3 = e4.w*inv;
            eacc += p0*__logf(p0 + 1e-8f) + p1*__logf(p1 + 1e-8f)
                  + p2*__logf(p2 + 1e-8f) + p3*__logf(p3 + 1e-8f);
            *(float4*)ep = make_float4(p0, p1, p2, p3);
            int kk = 4*kg4;
            sP[(kk+0)*20 + q] = p0;
            sP[(kk+1)*20 + q] = p1;
            sP[(kk+2)*20 + q] = p2;
            sP[(kk+3)*20 + q] = p3;
        }
        __syncthreads();
        const int kbase = g*32;
        #pragma unroll
        for (int t = 0; t < 32; t++) {
            int kk = kbase + t;
            float4 p = *(const float4*)&sP[kk*20 + 4*qg];
            float4 v = *(const float4*)&sV[kk*68 + 4*hg];
            float pv[4] = {p.x, p.y, p.z, p.w};
            float vv[4] = {v.x, v.y, v.z, v.w};
            #pragma unroll
            for (int i = 0; i < 4; i++)
                #pragma unroll
                for (int j = 0; j < 4; j++) acc[i][j] += pv[i] * vv[j];
        }
    }

    // cross-group reduction of out accumulators (reuse sV as scratch)
    __syncthreads();
    float* red = sV;               // needs 4*1024 floats = 16KB <= sV size
    #pragma unroll
    for (int i = 0; i < 4; i++)
        #pragma unroll
        for (int j = 0; j < 4; j++)
            red[g*1024 + (4*qg + i)*64 + 4*hg + j] = acc[i][j];
    __syncthreads();
    #pragma unroll
    for (int m = 0; m < 4; m++) {
        int e = tid + m*256;
        float v = red[e] + red[1024 + e] + red[2048 + e] + red[3072 + e];
        out[((size_t)b*TSEQ + q0 + (e >> 6))*HDIM + (e & 63)] = v;
    }

    // entropy reduction -> one atomicAdd per CTA
    #pragma unroll
    for (int off = 16; off > 0; off >>= 1)
        eacc += __shfl_xor_sync(0xffffffffu, eacc, off);
    if ((tid & 31) == 0) ered[tid >> 5] = eacc;
    __syncthreads();
    if (tid == 0) {
        float t = 0.f;
        #pragma unroll
        for (int w = 0; w < 8; w++) t += ered[w];
        atomicAdd(&g_ent, t);
    }
}

// ---------------------------------------------------------------------------
// K4: finalize energy EMA
// ---------------------------------------------------------------------------
__global__ void fin_kernel(const float* __restrict__ energy, float* __restrict__ eout)
{
    float ent_mean = -g_ent / (float)NROWS;
    *eout = 0.9f * energy[0] + 0.1f * ent_mean;
}

// ---------------------------------------------------------------------------
extern "C" void kernel_launch(void* const* d_in, const int* in_sizes, int n_in,
                              void* d_out, int out_size)
{
    const float* x      = (const float*)d_in[0];
    const float* Wq     = (const float*)d_in[1];
    const float* Wk     = (const float*)d_in[2];
    const float* Wv     = (const float*)d_in[3];
    const float* energy = (const float*)d_in[4];

    float* out  = (float*)d_out;                               // [B,T,H]
    float* attn = out + (size_t)BATCH*TSEQ*HDIM;               // [B,T,T]
    float* eout = attn + (size_t)BATCH*TSEQ*TSEQ;              // scalar

    zero_kernel<<<1, 1>>>();
    proj_kernel<<<dim3(NROWS/64, 3), 256>>>(x, Wq, Wk, Wv);
    score_kernel<<<dim3(TSEQ/TQ, BATCH), 256>>>(attn);
    av_kernel<<<dim3(TSEQ/TQ, BATCH), 256>>>(attn, out);
    fin_kernel<<<1, 1>>>(energy, eout);
}